// round 1
// baseline (speedup 1.0000x reference)
#include <cuda_runtime.h>

// NCykParser: neural CYK chart, n=16 tokens, R=64 rules, VOCAB=26.
// chart[L][s][r] = relu( max_{k,a,b} W[r,a,b] * chart[k][s][a] * chart[L-k][s+k][b] )
//
// Factorization (exact for nonnegative V, bit-exact under fp32 rounding since
// x -> rn(x*v) is monotone for v>=0):
//   max_{a,b} W[r,a,b]*U[a]*V[b] = max_b V[b] * M[r,b],  M[r,b] = max_a W[r,a,b]*U[a]
// M depends only on the LEFT child (k, s). A block pinned to (s, r-chunk)
// computes M for its own span at each level and keeps all of them in shared
// memory for the whole kernel (15 x 8 x 64 floats = 30KB). No global M.
//
// Single persistent kernel, 128 blocks (<= 148 SMs -> wave-1 co-resident),
// software grid barrier between levels. L1 persists across levels, so each
// block's 128KB W slice is L1-resident after the first level.

#define NTOK 16
#define R    64
#define NBLK 128
#define NTHR 256

__device__ __align__(256) float g_chart[NTOK + 1][NTOK][R];
__device__ unsigned g_count;
__device__ unsigned g_epoch;

__global__ void cyk_init_kernel() {
    g_count = 0u;
    g_epoch = 0u;
}

__device__ __forceinline__ void grid_barrier(unsigned target) {
    __syncthreads();
    if (threadIdx.x == 0) {
        __threadfence();
        if (atomicAdd(&g_count, 1u) == (unsigned)(gridDim.x - 1)) {
            g_count = 0u;          // safe: all blocks already arrived
            __threadfence();
            atomicAdd(&g_epoch, 1u);   // release
        } else {
            while (atomicAdd(&g_epoch, 0u) < target) {
                __nanosleep(32);
            }
        }
        __threadfence();           // acquire for subsequent chart reads
    }
    __syncthreads();
}

__global__ void __launch_bounds__(NTHR, 1) cyk_main_kernel(
    const int* __restrict__ tokens,
    const float* __restrict__ W,    // [R][R][R] row-major: W[r*4096 + a*64 + b]
    const float* __restrict__ E,    // [VOCAB][R]
    float* __restrict__ out)
{
    __shared__ __align__(16) float Msh[15][8][R];  // M for left-child len k=1..15, own 8 rules
    __shared__ float Ush[R];

    const int tid  = threadIdx.x;
    const int s    = blockIdx.x >> 3;   // span start 0..15 (fixed per block)
    const int rc   = blockIdx.x & 7;    // r-chunk 0..7   (fixed per block)
    const int r0   = rc << 3;           // first rule of chunk (8 rules/chunk)
    const int warp = tid >> 5;          // 0..7 -> rule index within chunk
    const int lane = tid & 31;

    // Level 1: chart[1][s] = E[tokens[s]]
    if (rc == 0 && tid < R) {
        int tok = tokens[s];
        g_chart[1][s][tid] = E[tok * R + tid];
    }
    grid_barrier(1u);

    for (int L = 2; L <= NTOK; ++L) {
        const int S = NTOK + 1 - L;     // spans at this level
        if (s < S) {
            // ---- Phase 1: M[L-1][s][r0..r0+7][b] = max_a W[r,a,b]*chart[L-1][s][a]
            if (tid < R) Ush[tid] = __ldcg(&g_chart[L - 1][s][tid]);
            __syncthreads();
            {
                const int ri   = warp;        // rule within chunk
                const int q    = lane & 15;   // b-quad: b = 4q..4q+3
                const int half = lane >> 4;   // a-half: a in [32*half, 32*half+32)
                const float* wp = W + (r0 + ri) * (R * R) + (half << 5) * R + (q << 2);
                float4 m = make_float4(-1e30f, -1e30f, -1e30f, -1e30f);
                #pragma unroll
                for (int a = 0; a < 32; ++a) {
                    float  u = Ush[(half << 5) + a];
                    float4 w = *(const float4*)(wp + (a << 6));
                    m.x = fmaxf(m.x, w.x * u);
                    m.y = fmaxf(m.y, w.y * u);
                    m.z = fmaxf(m.z, w.z * u);
                    m.w = fmaxf(m.w, w.w * u);
                }
                // combine the two a-halves (lanes l and l^16)
                m.x = fmaxf(m.x, __shfl_xor_sync(0xffffffffu, m.x, 16));
                m.y = fmaxf(m.y, __shfl_xor_sync(0xffffffffu, m.y, 16));
                m.z = fmaxf(m.z, __shfl_xor_sync(0xffffffffu, m.z, 16));
                m.w = fmaxf(m.w, __shfl_xor_sync(0xffffffffu, m.w, 16));
                if (half == 0) {
                    *(float4*)&Msh[L - 2][ri][q << 2] = m;
                }
            }
            __syncthreads();

            // ---- Phase 2: chart[L][s][r] = max(0, max_{k,b} Msh[k-1][r][b] * chart[L-k][s+k][b])
            {
                float best = 0.0f;   // relu floor
                for (int k = 1; k < L; ++k) {
                    const float* V = &g_chart[L - k][s + k][0];
                    float v1 = __ldcg(V + lane);
                    float v2 = __ldcg(V + lane + 32);
                    float m1 = Msh[k - 1][warp][lane];
                    float m2 = Msh[k - 1][warp][lane + 32];
                    best = fmaxf(best, m1 * v1);
                    best = fmaxf(best, m2 * v2);
                }
                #pragma unroll
                for (int off = 16; off; off >>= 1)
                    best = fmaxf(best, __shfl_xor_sync(0xffffffffu, best, off));
                if (lane == 0) {
                    g_chart[L][s][r0 + warp] = best;
                    if (L == NTOK && s == 0 && (r0 + warp) == 0)
                        out[0] = best;
                }
            }
        }
        if (L < NTOK) grid_barrier((unsigned)L);
    }
}

extern "C" void kernel_launch(void* const* d_in, const int* in_sizes, int n_in,
                              void* d_out, int out_size) {
    // Identify inputs by element count (robust to metadata order):
    // tokens: 16 int32, W: 64^3 = 262144 f32, E: 26*64 = 1664 f32
    const int*   tokens = (const int*)d_in[0];
    const float* W      = (const float*)d_in[1];
    const float* E      = (const float*)d_in[2];
    for (int i = 0; i < n_in; ++i) {
        if      (in_sizes[i] == 16)     tokens = (const int*)d_in[i];
        else if (in_sizes[i] == 262144) W      = (const float*)d_in[i];
        else if (in_sizes[i] == 1664)   E      = (const float*)d_in[i];
    }
    cyk_init_kernel<<<1, 1>>>();
    cyk_main_kernel<<<NBLK, NTHR>>>(tokens, W, E, (float*)d_out);
}